// round 2
// baseline (speedup 1.0000x reference)
#include <cuda_runtime.h>
#include <cstddef>

typedef unsigned long long ull;

// ---------------------------------------------------------------------------
// Packed f32x2 helpers (Blackwell sm_100+)
// ---------------------------------------------------------------------------
__device__ __forceinline__ ull bcast2(float a) {
    ull r; asm("mov.b64 %0, {%1, %1};" : "=l"(r) : "f"(a)); return r;
}
__device__ __forceinline__ void unpack2(ull v, float& a, float& b) {
    asm("mov.b64 {%0, %1}, %2;" : "=f"(a), "=f"(b) : "l"(v));
}
__device__ __forceinline__ ull fma2(ull a, ull b, ull c) {
    ull d; asm("fma.rn.f32x2 %0, %1, %2, %3;" : "=l"(d) : "l"(a), "l"(b), "l"(c));
    return d;
}
__device__ __forceinline__ float ex2_fast(float x) {
    float r; asm("ex2.approx.f32 %0, %1;" : "=f"(r) : "f"(x)); return r;
}
__device__ __forceinline__ float rcp_fast(float x) {
    float r; asm("rcp.approx.f32 %0, %1;" : "=f"(r) : "f"(x)); return r;
}
// accurate tanh: 1 - 2/(e^{2z}+1) from ex2/rcp (~1e-6 rel err)
__device__ __forceinline__ float tanh_acc(float z) {
    float e = ex2_fast(2.8853900817779268f * z);   // e^{2z}
    float r = rcp_fast(e + 1.0f);
    return fmaf(-2.0f, r, 1.0f);
}

// ---------------------------------------------------------------------------
// Layout constants
//   Per net (stride 2944 floats):
//     [0)    W1half [64][16]   [1024) b1[16]
//     [1040) W2 [16][16]       [1296) b2[16]
//     [1312) W3 [16][16]       [1568) b3[16]
//     [1584) W4 [16][16]       [1840) b4[16]
//     [1856) W5half [16][64]   [2880) b5half[64]
//   Layer = t-net + s-net = 5888 floats; 6 layers = 35328 floats (141.3 KB).
//   After weights: xs[64][NT] = masked-half staging (80 KB at NT=320).
// ---------------------------------------------------------------------------
#define NT 320
#define NET_STRIDE   2944
#define LAYER_STRIDE 5888
#define W_FLOATS     35328
#define XS_FLOATS    (64 * NT)
#define SMEM_BYTES   ((W_FLOATS + XS_FLOATS) * 4)

__device__ void load_net(float* L,
                         const float* W1, const float* b1,
                         const float* W2, const float* b2,
                         const float* W3, const float* b3,
                         const float* W4, const float* b4,
                         const float* W5, const float* b5,
                         int MOFF, int UOFF) {
    const int t = threadIdx.x;
    for (int idx = t; idx < 1024; idx += NT) L[idx] = W1[(MOFF << 4) + idx];
    for (int idx = t; idx < 16;   idx += NT) L[1024 + idx] = b1[idx];
    for (int idx = t; idx < 256;  idx += NT) L[1040 + idx] = W2[idx];
    for (int idx = t; idx < 16;   idx += NT) L[1296 + idx] = b2[idx];
    for (int idx = t; idx < 256;  idx += NT) L[1312 + idx] = W3[idx];
    for (int idx = t; idx < 16;   idx += NT) L[1568 + idx] = b3[idx];
    for (int idx = t; idx < 256;  idx += NT) L[1584 + idx] = W4[idx];
    for (int idx = t; idx < 16;   idx += NT) L[1840 + idx] = b4[idx];
    for (int idx = t; idx < 1024; idx += NT)
        L[1856 + idx] = W5[(idx >> 6) * 128 + UOFF + (idx & 63)];
    for (int idx = t; idx < 64;   idx += NT) L[2880 + idx] = b5[UOFF + idx];
}

// ---------------------------------------------------------------------------
// Hidden stack: h = relu(relu(relu(relu(xm@W1+b1)@W2+b2)@W3+b3)@W4+b4)
// xm read from shared (thread-private column, stride NT).
// ---------------------------------------------------------------------------
__device__ __forceinline__ void net_hidden(const float* __restrict__ xsp,
                                           const float* __restrict__ sw,
                                           float (&h)[16]) {
    ull acc[8];
    // layer 1: 64 -> 16
    {
        const ull* b = (const ull*)(sw + 1024);
        #pragma unroll
        for (int j = 0; j < 8; j++) acc[j] = b[j];
        const ulonglong2* W = (const ulonglong2*)sw;
        #pragma unroll 8
        for (int k = 0; k < 64; k++) {
            ull xk = bcast2(xsp[k * NT]);
            #pragma unroll
            for (int j = 0; j < 4; j++) {
                ulonglong2 w = W[k * 4 + j];
                acc[2 * j]     = fma2(xk, w.x, acc[2 * j]);
                acc[2 * j + 1] = fma2(xk, w.y, acc[2 * j + 1]);
            }
        }
        #pragma unroll
        for (int j = 0; j < 8; j++) {
            float a, bb; unpack2(acc[j], a, bb);
            h[2 * j]     = fmaxf(a, 0.0f);
            h[2 * j + 1] = fmaxf(bb, 0.0f);
        }
    }
    // layers 2..4: 16 -> 16
    #pragma unroll
    for (int l = 0; l < 3; l++) {
        const float* base = sw + 1040 + l * 272;
        const ulonglong2* W = (const ulonglong2*)base;
        const ull* b = (const ull*)(base + 256);
        #pragma unroll
        for (int j = 0; j < 8; j++) acc[j] = b[j];
        #pragma unroll
        for (int k = 0; k < 16; k++) {
            ull hk = bcast2(h[k]);
            #pragma unroll
            for (int j = 0; j < 4; j++) {
                ulonglong2 w = W[k * 4 + j];
                acc[2 * j]     = fma2(hk, w.x, acc[2 * j]);
                acc[2 * j + 1] = fma2(hk, w.y, acc[2 * j + 1]);
            }
        }
        #pragma unroll
        for (int j = 0; j < 8; j++) {
            float a, bb; unpack2(acc[j], a, bb);
            h[2 * j]     = fmaxf(a, 0.0f);
            h[2 * j + 1] = fmaxf(bb, 0.0f);
        }
    }
}

// Linear head: out[32] (ull = 64 floats) = h @ W5half + b5half
__device__ __forceinline__ void net_head(const float* __restrict__ sw,
                                         const float (&h)[16], ull (&out)[32]) {
    const ulonglong2* W5 = (const ulonglong2*)(sw + 1856);
    const ull* b5 = (const ull*)(sw + 2880);
    #pragma unroll
    for (int u = 0; u < 32; u++) out[u] = b5[u];
    #pragma unroll 4
    for (int k = 0; k < 16; k++) {
        ull hk = bcast2(h[k]);
        #pragma unroll
        for (int j = 0; j < 16; j++) {
            ulonglong2 w = W5[k * 16 + j];
            out[2 * j]     = fma2(hk, w.x, out[2 * j]);
            out[2 * j + 1] = fma2(hk, w.y, out[2 * j + 1]);
        }
    }
}

// One coupling layer (inverse): xr = (xr - t) * exp(-s); ld -= sum(s)
__device__ __forceinline__ void coupling(float (&xr)[64],
                                         const float* __restrict__ xsp,
                                         float& ld, const float* __restrict__ sw) {
    float h[16];
    ull o[32];

    // t net
    net_hidden(xsp, sw, h);
    net_head(sw, h, o);
    #pragma unroll
    for (int j = 0; j < 32; j++) {
        float a, b; unpack2(o[j], a, b);
        xr[2 * j]     -= a;
        xr[2 * j + 1] -= b;
    }

    // s net
    const float* ss = sw + NET_STRIDE;
    net_hidden(xsp, ss, h);
    net_head(ss, h, o);
    #pragma unroll
    for (int j = 0; j < 32; j++) {
        float a, b; unpack2(o[j], a, b);
        float s0 = tanh_acc(a);
        float s1 = tanh_acc(b);
        xr[2 * j]     *= ex2_fast(-1.4426950408889634f * s0);
        xr[2 * j + 1] *= ex2_fast(-1.4426950408889634f * s1);
        ld -= (s0 + s1);
    }
}

// ---------------------------------------------------------------------------
// Fused kernel. Updated half lives in registers; masked half in smem column.
// ---------------------------------------------------------------------------
__global__ void __launch_bounds__(NT, 1)
realnvp_kernel(const float* __restrict__ x_in,
               const float* __restrict__ tW1, const float* __restrict__ tb1,
               const float* __restrict__ tW2, const float* __restrict__ tb2,
               const float* __restrict__ tW3, const float* __restrict__ tb3,
               const float* __restrict__ tW4, const float* __restrict__ tb4,
               const float* __restrict__ tW5, const float* __restrict__ tb5,
               const float* __restrict__ sW1, const float* __restrict__ sb1,
               const float* __restrict__ sW2, const float* __restrict__ sb2,
               const float* __restrict__ sW3, const float* __restrict__ sb3,
               const float* __restrict__ sW4, const float* __restrict__ sb4,
               const float* __restrict__ sW5, const float* __restrict__ sb5,
               float* __restrict__ y_out, float* __restrict__ ld_out, int B) {
    extern __shared__ float smw[];

    // Stage pruned weights. Processed layer i uses original layer p = 5-i.
    // i even -> masked half [0,64) (MOFF=0, UOFF=64); i odd -> MOFF=64, UOFF=0.
    #pragma unroll 1
    for (int i = 0; i < 6; i++) {
        const int p = 5 - i;
        const int MOFF = (i & 1) ? 64 : 0;
        const int UOFF = 64 - MOFF;
        float* L = smw + i * LAYER_STRIDE;
        load_net(L,
                 tW1 + p * 2048, tb1 + p * 16, tW2 + p * 256, tb2 + p * 16,
                 tW3 + p * 256,  tb3 + p * 16, tW4 + p * 256, tb4 + p * 16,
                 tW5 + p * 2048, tb5 + p * 128, MOFF, UOFF);
        load_net(L + NET_STRIDE,
                 sW1 + p * 2048, sb1 + p * 16, sW2 + p * 256, sb2 + p * 16,
                 sW3 + p * 256,  sb3 + p * 16, sW4 + p * 256, sb4 + p * 16,
                 sW5 + p * 2048, sb5 + p * 128, MOFF, UOFF);
    }
    __syncthreads();

    float* xsp = smw + W_FLOATS + threadIdx.x;   // thread-private column
    const int stride = gridDim.x * NT;
    for (int r = blockIdx.x * NT + threadIdx.x; r < B; r += stride) {
        const float4* xi = (const float4*)(x_in + (size_t)r * 128);
        // masked half of layer 0 = x[0:64) -> smem; updated half -> regs
        #pragma unroll
        for (int q = 0; q < 16; q++) {
            float4 v = xi[q];
            xsp[(4 * q + 0) * NT] = v.x;
            xsp[(4 * q + 1) * NT] = v.y;
            xsp[(4 * q + 2) * NT] = v.z;
            xsp[(4 * q + 3) * NT] = v.w;
        }
        float xr[64];
        #pragma unroll
        for (int q = 0; q < 16; q++) {
            float4 v = xi[16 + q];
            xr[4 * q + 0] = v.x; xr[4 * q + 1] = v.y;
            xr[4 * q + 2] = v.z; xr[4 * q + 3] = v.w;
        }

        float ld = 0.0f;
        #pragma unroll 1
        for (int i = 0; i < 6; i++) {
            coupling(xr, xsp, ld, smw + i * LAYER_STRIDE);
            if (i < 5) {
                // role swap: updated half becomes next layer's masked half
                #pragma unroll
                for (int k = 0; k < 64; k++) {
                    float tmp = xsp[k * NT];
                    xsp[k * NT] = xr[k];
                    xr[k] = tmp;
                }
            }
        }

        // After layer 5 (MOFF=64): xr = y[0:64), xs = y[64:128)
        float4* yo = (float4*)(y_out + (size_t)r * 128);
        #pragma unroll
        for (int q = 0; q < 16; q++)
            yo[q] = make_float4(xr[4 * q], xr[4 * q + 1],
                                xr[4 * q + 2], xr[4 * q + 3]);
        #pragma unroll
        for (int q = 0; q < 16; q++)
            yo[16 + q] = make_float4(xsp[(4 * q + 0) * NT], xsp[(4 * q + 1) * NT],
                                     xsp[(4 * q + 2) * NT], xsp[(4 * q + 3) * NT]);
        ld_out[r] = ld;
    }
}

// ---------------------------------------------------------------------------
// Harness entry point.
// Input order: x, masks, tW1,tb1,...,tW5,tb5, sW1,sb1,...,sW5,sb5
// Output: y [B,128] followed by logdet [B]
// ---------------------------------------------------------------------------
extern "C" void kernel_launch(void* const* d_in, const int* in_sizes, int n_in,
                              void* d_out, int out_size) {
    const float* x = (const float*)d_in[0];
    const float* P[20];
    for (int i = 0; i < 20; i++) P[i] = (const float*)d_in[2 + i];

    const int B = in_sizes[0] / 128;
    float* y  = (float*)d_out;
    float* ld = y + (size_t)B * 128;

    cudaFuncSetAttribute(realnvp_kernel,
                         cudaFuncAttributeMaxDynamicSharedMemorySize, SMEM_BYTES);

    dim3 grid(148), block(NT);
    realnvp_kernel<<<grid, block, SMEM_BYTES>>>(
        x,
        P[0], P[1], P[2], P[3], P[4], P[5], P[6], P[7], P[8], P[9],
        P[10], P[11], P[12], P[13], P[14], P[15], P[16], P[17], P[18], P[19],
        y, ld, B);
}

// round 6
// speedup vs baseline: 1.1797x; 1.1797x over previous
#include <cuda_runtime.h>
#include <cstddef>

typedef unsigned long long ull;

// ---------------------------------------------------------------------------
// Packed f32x2 helpers (Blackwell sm_100+)
// ---------------------------------------------------------------------------
__device__ __forceinline__ ull bcast2(float a) {
    ull r; asm("mov.b64 %0, {%1, %1};" : "=l"(r) : "f"(a)); return r;
}
__device__ __forceinline__ void unpack2(ull v, float& a, float& b) {
    asm("mov.b64 {%0, %1}, %2;" : "=f"(a), "=f"(b) : "l"(v));
}
__device__ __forceinline__ ull fma2(ull a, ull b, ull c) {
    ull d; asm("fma.rn.f32x2 %0, %1, %2, %3;" : "=l"(d) : "l"(a), "l"(b), "l"(c));
    return d;
}
__device__ __forceinline__ float ex2_fast(float x) {
    float r; asm("ex2.approx.f32 %0, %1;" : "=f"(r) : "f"(x)); return r;
}
__device__ __forceinline__ float rcp_fast(float x) {
    float r; asm("rcp.approx.f32 %0, %1;" : "=f"(r) : "f"(x)); return r;
}
// accurate tanh: 1 - 2/(e^{2z}+1) from ex2/rcp (~1e-6 rel err)
__device__ __forceinline__ float tanh_acc(float z) {
    float e = ex2_fast(2.8853900817779268f * z);   // e^{2z}
    float r = rcp_fast(e + 1.0f);
    return fmaf(-2.0f, r, 1.0f);
}

// ---------------------------------------------------------------------------
// Per-net smem layout (floats), stride 2944:
//   [0)    W1half [64][16]   [1024) b1[16]
//   [1040) W2 [16][16]       [1296) b2[16]
//   [1312) W3 [16][16]       [1568) b3[16]
//   [1584) W4 [16][16]       [1840) b4[16]
//   [1856) W5half [16][64]   [2880) b5half[64]
// One layer = t-net + s-net = 5888 floats = 23.5 KB.
// ---------------------------------------------------------------------------
#define TPB 128
#define NET_STRIDE 2944

__device__ void load_net(float* L,
                         const float* W1, const float* b1,
                         const float* W2, const float* b2,
                         const float* W3, const float* b3,
                         const float* W4, const float* b4,
                         const float* W5, const float* b5,
                         int MOFF, int UOFF) {
    const int t = threadIdx.x;
    for (int idx = t; idx < 1024; idx += TPB) L[idx] = W1[(MOFF << 4) + idx];
    for (int idx = t; idx < 16;   idx += TPB) L[1024 + idx] = b1[idx];
    for (int idx = t; idx < 256;  idx += TPB) L[1040 + idx] = W2[idx];
    for (int idx = t; idx < 16;   idx += TPB) L[1296 + idx] = b2[idx];
    for (int idx = t; idx < 256;  idx += TPB) L[1312 + idx] = W3[idx];
    for (int idx = t; idx < 16;   idx += TPB) L[1568 + idx] = b3[idx];
    for (int idx = t; idx < 256;  idx += TPB) L[1584 + idx] = W4[idx];
    for (int idx = t; idx < 16;   idx += TPB) L[1840 + idx] = b4[idx];
    for (int idx = t; idx < 1024; idx += TPB)
        L[1856 + idx] = W5[(idx >> 6) * 128 + UOFF + (idx & 63)];
    for (int idx = t; idx < 64;   idx += TPB) L[2880 + idx] = b5[UOFF + idx];
}

// ---------------------------------------------------------------------------
// One coupling layer for all rows. t-net and s-net computed interleaved
// (2 independent FMA chains). Masked half streamed from gmem; unmasked half
// streamed + updated chunk-wise. One thread = one row.
// ---------------------------------------------------------------------------
template<int MOFF, bool FIRST>
__global__ void __launch_bounds__(TPB, 4)
layer_kernel(const float* __restrict__ x_in,
             const float* __restrict__ tW1, const float* __restrict__ tb1,
             const float* __restrict__ tW2, const float* __restrict__ tb2,
             const float* __restrict__ tW3, const float* __restrict__ tb3,
             const float* __restrict__ tW4, const float* __restrict__ tb4,
             const float* __restrict__ tW5, const float* __restrict__ tb5,
             const float* __restrict__ sW1, const float* __restrict__ sb1,
             const float* __restrict__ sW2, const float* __restrict__ sb2,
             const float* __restrict__ sW3, const float* __restrict__ sb3,
             const float* __restrict__ sW4, const float* __restrict__ sb4,
             const float* __restrict__ sW5, const float* __restrict__ sb5,
             float* __restrict__ y, float* __restrict__ ld_out, int B) {
    constexpr int UOFF = 64 - MOFF;
    __shared__ float sw[2 * NET_STRIDE];

    load_net(sw, tW1, tb1, tW2, tb2, tW3, tb3, tW4, tb4, tW5, tb5, MOFF, UOFF);
    load_net(sw + NET_STRIDE,
             sW1, sb1, sW2, sb2, sW3, sb3, sW4, sb4, sW5, sb5, MOFF, UOFF);
    __syncthreads();

    const int r = blockIdx.x * TPB + threadIdx.x;
    if (r >= B) return;
    const float* xr = x_in + (size_t)r * 128;
    float*       yr = y    + (size_t)r * 128;

    // ---- layer 1 (64 -> 16), t & s interleaved, x streamed from gmem ----
    float hT[16], hS[16];
    {
        const ulonglong2* WT = (const ulonglong2*)(sw);
        const ulonglong2* WS = (const ulonglong2*)(sw + NET_STRIDE);
        const ull* bT = (const ull*)(sw + 1024);
        const ull* bS = (const ull*)(sw + NET_STRIDE + 1024);
        ull aT[8], aS[8];
        #pragma unroll
        for (int j = 0; j < 8; j++) { aT[j] = bT[j]; aS[j] = bS[j]; }
        #pragma unroll
        for (int q = 0; q < 16; q++) {
            float4 xv = *(const float4*)(xr + MOFF + 4 * q);
            if (FIRST)   // copy masked half into output row once
                *(float4*)(yr + MOFF + 4 * q) = xv;
            float xs4[4] = {xv.x, xv.y, xv.z, xv.w};
            #pragma unroll
            for (int kk = 0; kk < 4; kk++) {
                const int k = 4 * q + kk;
                ull xk = bcast2(xs4[kk]);
                #pragma unroll
                for (int j = 0; j < 4; j++) {
                    ulonglong2 wt = WT[k * 4 + j];
                    aT[2 * j]     = fma2(xk, wt.x, aT[2 * j]);
                    aT[2 * j + 1] = fma2(xk, wt.y, aT[2 * j + 1]);
                    ulonglong2 ws = WS[k * 4 + j];
                    aS[2 * j]     = fma2(xk, ws.x, aS[2 * j]);
                    aS[2 * j + 1] = fma2(xk, ws.y, aS[2 * j + 1]);
                }
            }
        }
        #pragma unroll
        for (int j = 0; j < 8; j++) {
            float a, b;
            unpack2(aT[j], a, b);
            hT[2 * j] = fmaxf(a, 0.0f); hT[2 * j + 1] = fmaxf(b, 0.0f);
            unpack2(aS[j], a, b);
            hS[2 * j] = fmaxf(a, 0.0f); hS[2 * j + 1] = fmaxf(b, 0.0f);
        }
    }

    // ---- layers 2..4 (16 -> 16), interleaved ----
    #pragma unroll
    for (int l = 0; l < 3; l++) {
        const float* baseT = sw + 1040 + l * 272;
        const float* baseS = baseT + NET_STRIDE;
        const ulonglong2* WT = (const ulonglong2*)baseT;
        const ulonglong2* WS = (const ulonglong2*)baseS;
        const ull* bT = (const ull*)(baseT + 256);
        const ull* bS = (const ull*)(baseS + 256);
        ull aT[8], aS[8];
        #pragma unroll
        for (int j = 0; j < 8; j++) { aT[j] = bT[j]; aS[j] = bS[j]; }
        #pragma unroll
        for (int k = 0; k < 16; k++) {
            ull tk = bcast2(hT[k]);
            ull sk = bcast2(hS[k]);
            #pragma unroll
            for (int j = 0; j < 4; j++) {
                ulonglong2 wt = WT[k * 4 + j];
                aT[2 * j]     = fma2(tk, wt.x, aT[2 * j]);
                aT[2 * j + 1] = fma2(tk, wt.y, aT[2 * j + 1]);
                ulonglong2 ws = WS[k * 4 + j];
                aS[2 * j]     = fma2(sk, ws.x, aS[2 * j]);
                aS[2 * j + 1] = fma2(sk, ws.y, aS[2 * j + 1]);
            }
        }
        #pragma unroll
        for (int j = 0; j < 8; j++) {
            float a, b;
            unpack2(aT[j], a, b);
            hT[2 * j] = fmaxf(a, 0.0f); hT[2 * j + 1] = fmaxf(b, 0.0f);
            unpack2(aS[j], a, b);
            hS[2 * j] = fmaxf(a, 0.0f); hS[2 * j + 1] = fmaxf(b, 0.0f);
        }
    }

    // ---- heads (16 -> 64) in 4 chunks of 16, apply inverse transform ----
    const ulonglong2* W5T = (const ulonglong2*)(sw + 1856);
    const ulonglong2* W5S = (const ulonglong2*)(sw + NET_STRIDE + 1856);
    const ull* b5T = (const ull*)(sw + 2880);
    const ull* b5S = (const ull*)(sw + NET_STRIDE + 2880);
    float ldsum = 0.0f;
    #pragma unroll
    for (int c = 0; c < 4; c++) {
        ull oT[8], oS[8];
        #pragma unroll
        for (int u = 0; u < 8; u++) { oT[u] = b5T[c * 8 + u]; oS[u] = b5S[c * 8 + u]; }
        #pragma unroll
        for (int k = 0; k < 16; k++) {
            ull tk = bcast2(hT[k]);
            ull sk = bcast2(hS[k]);
            #pragma unroll
            for (int j = 0; j < 4; j++) {
                ulonglong2 wt = W5T[k * 16 + c * 4 + j];
                oT[2 * j]     = fma2(tk, wt.x, oT[2 * j]);
                oT[2 * j + 1] = fma2(tk, wt.y, oT[2 * j + 1]);
                ulonglong2 ws = W5S[k * 16 + c * 4 + j];
                oS[2 * j]     = fma2(sk, ws.x, oS[2 * j]);
                oS[2 * j + 1] = fma2(sk, ws.y, oS[2 * j + 1]);
            }
        }
        float xu[16];
        #pragma unroll
        for (int q = 0; q < 4; q++) {
            float4 v = *(const float4*)(xr + UOFF + c * 16 + 4 * q);
            xu[4 * q] = v.x; xu[4 * q + 1] = v.y;
            xu[4 * q + 2] = v.z; xu[4 * q + 3] = v.w;
        }
        #pragma unroll
        for (int u = 0; u < 8; u++) {
            float t0, t1, z0, z1;
            unpack2(oT[u], t0, t1);
            unpack2(oS[u], z0, z1);
            float s0 = tanh_acc(z0);
            float s1 = tanh_acc(z1);
            xu[2 * u]     = (xu[2 * u]     - t0) * ex2_fast(-1.4426950408889634f * s0);
            xu[2 * u + 1] = (xu[2 * u + 1] - t1) * ex2_fast(-1.4426950408889634f * s1);
            ldsum += (s0 + s1);
        }
        #pragma unroll
        for (int q = 0; q < 4; q++)
            *(float4*)(yr + UOFF + c * 16 + 4 * q) =
                make_float4(xu[4 * q], xu[4 * q + 1], xu[4 * q + 2], xu[4 * q + 3]);
    }
    ld_out[r] = (FIRST ? 0.0f : ld_out[r]) - ldsum;
}

// ---------------------------------------------------------------------------
// Harness entry: 6 sequential per-layer launches (graph-capturable; no
// memcpy, no symbol writes — pointers passed as kernel arguments only).
// Input order: x, masks, tW1,tb1,...,tW5,tb5, sW1,sb1,...,sW5,sb5
// Output: y [B,128] then logdet [B]
// ---------------------------------------------------------------------------
extern "C" void kernel_launch(void* const* d_in, const int* in_sizes, int n_in,
                              void* d_out, int out_size) {
    const float* x = (const float*)d_in[0];
    const float* P[20];
    for (int i = 0; i < 20; i++) P[i] = (const float*)d_in[2 + i];

    const int B = in_sizes[0] / 128;
    float* y  = (float*)d_out;
    float* ld = y + (size_t)B * 128;

    const dim3 grid((B + TPB - 1) / TPB), block(TPB);

    // Processed layer i uses original layer p = 5 - i.
    // i even: masked half [0,64) (MOFF=0); i odd: MOFF=64.
#define ARGS(p)                                                              \
    P[0] + (p) * 2048, P[1] + (p) * 16,  P[2] + (p) * 256, P[3] + (p) * 16,  \
    P[4] + (p) * 256,  P[5] + (p) * 16,  P[6] + (p) * 256, P[7] + (p) * 16,  \
    P[8] + (p) * 2048, P[9] + (p) * 128,                                     \
    P[10] + (p) * 2048, P[11] + (p) * 16, P[12] + (p) * 256, P[13] + (p) * 16,\
    P[14] + (p) * 256,  P[15] + (p) * 16, P[16] + (p) * 256, P[17] + (p) * 16,\
    P[18] + (p) * 2048, P[19] + (p) * 128

    layer_kernel<0,  true ><<<grid, block>>>(x, ARGS(5), y, ld, B);
    layer_kernel<64, false><<<grid, block>>>(y, ARGS(4), y, ld, B);
    layer_kernel<0,  false><<<grid, block>>>(y, ARGS(3), y, ld, B);
    layer_kernel<64, false><<<grid, block>>>(y, ARGS(2), y, ld, B);
    layer_kernel<0,  false><<<grid, block>>>(y, ARGS(1), y, ld, B);
    layer_kernel<64, false><<<grid, block>>>(y, ARGS(0), y, ld, B);
#undef ARGS
}

// round 7
// speedup vs baseline: 1.2087x; 1.0246x over previous
#include <cuda_runtime.h>
#include <cstddef>

typedef unsigned long long ull;

// ---------------------------------------------------------------------------
// Packed f32x2 helpers (Blackwell sm_100+)
// ---------------------------------------------------------------------------
__device__ __forceinline__ ull bcast2(float a) {
    ull r; asm("mov.b64 %0, {%1, %1};" : "=l"(r) : "f"(a)); return r;
}
__device__ __forceinline__ void unpack2(ull v, float& a, float& b) {
    asm("mov.b64 {%0, %1}, %2;" : "=f"(a), "=f"(b) : "l"(v));
}
__device__ __forceinline__ ull fma2(ull a, ull b, ull c) {
    ull d; asm("fma.rn.f32x2 %0, %1, %2, %3;" : "=l"(d) : "l"(a), "l"(b), "l"(c));
    return d;
}
__device__ __forceinline__ float ex2_fast(float x) {
    float r; asm("ex2.approx.f32 %0, %1;" : "=f"(r) : "f"(x)); return r;
}
__device__ __forceinline__ float rcp_fast(float x) {
    float r; asm("rcp.approx.f32 %0, %1;" : "=f"(r) : "f"(x)); return r;
}
// accurate tanh: 1 - 2/(e^{2z}+1) from ex2/rcp (~1e-6 rel err)
__device__ __forceinline__ float tanh_acc(float z) {
    float e = ex2_fast(2.8853900817779268f * z);   // e^{2z}
    float r = rcp_fast(e + 1.0f);
    return fmaf(-2.0f, r, 1.0f);
}

// ---------------------------------------------------------------------------
// Per-net smem layout (floats), stride 2944:
//   [0)    W1half [64][16]   [1024) b1[16]
//   [1040) W2 [16][16]       [1296) b2[16]
//   [1312) W3 [16][16]       [1568) b3[16]
//   [1584) W4 [16][16]       [1840) b4[16]
//   [1856) W5half [16][64]   [2880) b5half[64]
// One layer = t-net + s-net = 5888 floats = 23.5 KB.
// ---------------------------------------------------------------------------
#define TPB 128
#define R   4          // rows per thread (amortizes weight LDS over rows)
#define NET_STRIDE 2944

__device__ void load_net(float* L,
                         const float* W1, const float* b1,
                         const float* W2, const float* b2,
                         const float* W3, const float* b3,
                         const float* W4, const float* b4,
                         const float* W5, const float* b5,
                         int MOFF, int UOFF) {
    const int t = threadIdx.x;
    for (int idx = t; idx < 1024; idx += TPB) L[idx] = W1[(MOFF << 4) + idx];
    for (int idx = t; idx < 16;   idx += TPB) L[1024 + idx] = b1[idx];
    for (int idx = t; idx < 256;  idx += TPB) L[1040 + idx] = W2[idx];
    for (int idx = t; idx < 16;   idx += TPB) L[1296 + idx] = b2[idx];
    for (int idx = t; idx < 256;  idx += TPB) L[1312 + idx] = W3[idx];
    for (int idx = t; idx < 16;   idx += TPB) L[1568 + idx] = b3[idx];
    for (int idx = t; idx < 256;  idx += TPB) L[1584 + idx] = W4[idx];
    for (int idx = t; idx < 16;   idx += TPB) L[1840 + idx] = b4[idx];
    for (int idx = t; idx < 1024; idx += TPB)
        L[1856 + idx] = W5[(idx >> 6) * 128 + UOFF + (idx & 63)];
    for (int idx = t; idx < 64;   idx += TPB) L[2880 + idx] = b5[UOFF + idx];
}

// Mid layers 2..4 (16 -> 16) for one net over R rows; h updated in place.
__device__ __forceinline__ void mid_layers(const float* __restrict__ swn,
                                           float (&h)[R][16]) {
    #pragma unroll 1
    for (int l = 0; l < 3; l++) {
        const ulonglong2* W = (const ulonglong2*)(swn + 1040 + l * 272);
        const ull* b = (const ull*)(swn + 1040 + l * 272 + 256);
        ull a[R][8];
        #pragma unroll
        for (int i = 0; i < R; i++)
            #pragma unroll
            for (int j = 0; j < 8; j++) a[i][j] = b[j];
        #pragma unroll
        for (int k = 0; k < 16; k++) {
            ull hk[R];
            #pragma unroll
            for (int i = 0; i < R; i++) hk[i] = bcast2(h[i][k]);
            #pragma unroll
            for (int j = 0; j < 4; j++) {
                ulonglong2 w = W[k * 4 + j];
                #pragma unroll
                for (int i = 0; i < R; i++) {
                    a[i][2 * j]     = fma2(hk[i], w.x, a[i][2 * j]);
                    a[i][2 * j + 1] = fma2(hk[i], w.y, a[i][2 * j + 1]);
                }
            }
        }
        #pragma unroll
        for (int i = 0; i < R; i++)
            #pragma unroll
            for (int j = 0; j < 8; j++) {
                float u, v; unpack2(a[i][j], u, v);
                h[i][2 * j]     = fmaxf(u, 0.0f);
                h[i][2 * j + 1] = fmaxf(v, 0.0f);
            }
    }
}

// ---------------------------------------------------------------------------
// One coupling layer, R rows per thread. Layer 1 interleaves t & s nets;
// mid layers run per-net; head in 8 chunks of 8 outputs.
// ---------------------------------------------------------------------------
template<int MOFF, bool FIRST>
__global__ void __launch_bounds__(TPB, 2)
layer_kernel(const float* __restrict__ x_in,
             const float* __restrict__ tW1, const float* __restrict__ tb1,
             const float* __restrict__ tW2, const float* __restrict__ tb2,
             const float* __restrict__ tW3, const float* __restrict__ tb3,
             const float* __restrict__ tW4, const float* __restrict__ tb4,
             const float* __restrict__ tW5, const float* __restrict__ tb5,
             const float* __restrict__ sW1, const float* __restrict__ sb1,
             const float* __restrict__ sW2, const float* __restrict__ sb2,
             const float* __restrict__ sW3, const float* __restrict__ sb3,
             const float* __restrict__ sW4, const float* __restrict__ sb4,
             const float* __restrict__ sW5, const float* __restrict__ sb5,
             float* __restrict__ y, float* __restrict__ ld_out, int B) {
    constexpr int UOFF = 64 - MOFF;
    __shared__ float sw[2 * NET_STRIDE];

    load_net(sw, tW1, tb1, tW2, tb2, tW3, tb3, tW4, tb4, tW5, tb5, MOFF, UOFF);
    load_net(sw + NET_STRIDE,
             sW1, sb1, sW2, sb2, sW3, sb3, sW4, sb4, sW5, sb5, MOFF, UOFF);
    __syncthreads();

    const int base = blockIdx.x * (TPB * R) + threadIdx.x;
    const float* xp[R];
    float* yp[R];
    bool ok[R];
    #pragma unroll
    for (int i = 0; i < R; i++) {
        int row = base + i * TPB;
        ok[i] = row < B;
        int rc = ok[i] ? row : 0;
        xp[i] = x_in + (size_t)rc * 128;
        yp[i] = y    + (size_t)rc * 128;
    }

    // ---- layer 1 (64 -> 16), t & s interleaved, x streamed from gmem ----
    float hT[R][16], hS[R][16];
    {
        const ulonglong2* WT = (const ulonglong2*)sw;
        const ulonglong2* WS = (const ulonglong2*)(sw + NET_STRIDE);
        const ull* bT = (const ull*)(sw + 1024);
        const ull* bS = (const ull*)(sw + NET_STRIDE + 1024);
        ull aT[R][8], aS[R][8];
        #pragma unroll
        for (int i = 0; i < R; i++)
            #pragma unroll
            for (int j = 0; j < 8; j++) { aT[i][j] = bT[j]; aS[i][j] = bS[j]; }
        #pragma unroll 1
        for (int q = 0; q < 16; q++) {
            float4 xv[R];
            #pragma unroll
            for (int i = 0; i < R; i++) {
                xv[i] = *(const float4*)(xp[i] + MOFF + 4 * q);
                if (FIRST && ok[i])      // copy masked half into output once
                    *(float4*)(yp[i] + MOFF + 4 * q) = xv[i];
            }
            #pragma unroll
            for (int kk = 0; kk < 4; kk++) {
                const int k = 4 * q + kk;
                ull xk[R];
                #pragma unroll
                for (int i = 0; i < R; i++)
                    xk[i] = bcast2(((const float*)&xv[i])[kk]);
                #pragma unroll
                for (int j = 0; j < 4; j++) {
                    ulonglong2 wt = WT[k * 4 + j];
                    #pragma unroll
                    for (int i = 0; i < R; i++) {
                        aT[i][2 * j]     = fma2(xk[i], wt.x, aT[i][2 * j]);
                        aT[i][2 * j + 1] = fma2(xk[i], wt.y, aT[i][2 * j + 1]);
                    }
                    ulonglong2 ws = WS[k * 4 + j];
                    #pragma unroll
                    for (int i = 0; i < R; i++) {
                        aS[i][2 * j]     = fma2(xk[i], ws.x, aS[i][2 * j]);
                        aS[i][2 * j + 1] = fma2(xk[i], ws.y, aS[i][2 * j + 1]);
                    }
                }
            }
        }
        #pragma unroll
        for (int i = 0; i < R; i++)
            #pragma unroll
            for (int j = 0; j < 8; j++) {
                float u, v;
                unpack2(aT[i][j], u, v);
                hT[i][2 * j]     = fmaxf(u, 0.0f);
                hT[i][2 * j + 1] = fmaxf(v, 0.0f);
                unpack2(aS[i][j], u, v);
                hS[i][2 * j]     = fmaxf(u, 0.0f);
                hS[i][2 * j + 1] = fmaxf(v, 0.0f);
            }
    }

    // ---- mid layers, per net (keeps register peak down) ----
    mid_layers(sw, hT);
    mid_layers(sw + NET_STRIDE, hS);

    // ---- head (16 -> 64), 8 chunks of 8 outputs, apply inverse transform ----
    const ulonglong2* W5T = (const ulonglong2*)(sw + 1856);
    const ulonglong2* W5S = (const ulonglong2*)(sw + NET_STRIDE + 1856);
    const ull* b5T = (const ull*)(sw + 2880);
    const ull* b5S = (const ull*)(sw + NET_STRIDE + 2880);
    float ldsum[R];
    #pragma unroll
    for (int i = 0; i < R; i++) ldsum[i] = 0.0f;

    #pragma unroll 1
    for (int c = 0; c < 8; c++) {
        // t chunk
        float tv[R][8];
        {
            ull oT[R][4];
            #pragma unroll
            for (int i = 0; i < R; i++)
                #pragma unroll
                for (int u = 0; u < 4; u++) oT[i][u] = b5T[c * 4 + u];
            #pragma unroll
            for (int k = 0; k < 16; k++) {
                ull tk[R];
                #pragma unroll
                for (int i = 0; i < R; i++) tk[i] = bcast2(hT[i][k]);
                #pragma unroll
                for (int j = 0; j < 2; j++) {
                    ulonglong2 w = W5T[k * 16 + c * 2 + j];
                    #pragma unroll
                    for (int i = 0; i < R; i++) {
                        oT[i][2 * j]     = fma2(tk[i], w.x, oT[i][2 * j]);
                        oT[i][2 * j + 1] = fma2(tk[i], w.y, oT[i][2 * j + 1]);
                    }
                }
            }
            #pragma unroll
            for (int i = 0; i < R; i++)
                #pragma unroll
                for (int u = 0; u < 4; u++)
                    unpack2(oT[i][u], tv[i][2 * u], tv[i][2 * u + 1]);
        }
        // s chunk
        ull oS[R][4];
        #pragma unroll
        for (int i = 0; i < R; i++)
            #pragma unroll
            for (int u = 0; u < 4; u++) oS[i][u] = b5S[c * 4 + u];
        #pragma unroll
        for (int k = 0; k < 16; k++) {
            ull sk[R];
            #pragma unroll
            for (int i = 0; i < R; i++) sk[i] = bcast2(hS[i][k]);
            #pragma unroll
            for (int j = 0; j < 2; j++) {
                ulonglong2 w = W5S[k * 16 + c * 2 + j];
                #pragma unroll
                for (int i = 0; i < R; i++) {
                    oS[i][2 * j]     = fma2(sk[i], w.x, oS[i][2 * j]);
                    oS[i][2 * j + 1] = fma2(sk[i], w.y, oS[i][2 * j + 1]);
                }
            }
        }
        // apply: xu = (xu - t) * exp(-s); ldsum += s
        #pragma unroll
        for (int i = 0; i < R; i++) {
            float4 v0 = *(const float4*)(xp[i] + UOFF + c * 8);
            float4 v1 = *(const float4*)(xp[i] + UOFF + c * 8 + 4);
            float xu[8] = {v0.x, v0.y, v0.z, v0.w, v1.x, v1.y, v1.z, v1.w};
            #pragma unroll
            for (int u = 0; u < 4; u++) {
                float z0, z1;
                unpack2(oS[i][u], z0, z1);
                float s0 = tanh_acc(z0);
                float s1 = tanh_acc(z1);
                xu[2 * u]     = (xu[2 * u]     - tv[i][2 * u])
                                * ex2_fast(-1.4426950408889634f * s0);
                xu[2 * u + 1] = (xu[2 * u + 1] - tv[i][2 * u + 1])
                                * ex2_fast(-1.4426950408889634f * s1);
                ldsum[i] += (s0 + s1);
            }
            if (ok[i]) {
                *(float4*)(yp[i] + UOFF + c * 8)     =
                    make_float4(xu[0], xu[1], xu[2], xu[3]);
                *(float4*)(yp[i] + UOFF + c * 8 + 4) =
                    make_float4(xu[4], xu[5], xu[6], xu[7]);
            }
        }
    }

    #pragma unroll
    for (int i = 0; i < R; i++) {
        int row = base + i * TPB;
        if (ok[i])
            ld_out[row] = (FIRST ? 0.0f : ld_out[row]) - ldsum[i];
    }
}

// ---------------------------------------------------------------------------
// Harness entry: 6 sequential per-layer launches (graph-capturable; pointers
// passed as kernel arguments only).
// Input order: x, masks, tW1,tb1,...,tW5,tb5, sW1,sb1,...,sW5,sb5
// Output: y [B,128] then logdet [B]
// ---------------------------------------------------------------------------
extern "C" void kernel_launch(void* const* d_in, const int* in_sizes, int n_in,
                              void* d_out, int out_size) {
    const float* x = (const float*)d_in[0];
    const float* P[20];
    for (int i = 0; i < 20; i++) P[i] = (const float*)d_in[2 + i];

    const int B = in_sizes[0] / 128;
    float* y  = (float*)d_out;
    float* ld = y + (size_t)B * 128;

    const int ROWS_PER_BLOCK = TPB * R;
    const dim3 grid((B + ROWS_PER_BLOCK - 1) / ROWS_PER_BLOCK), block(TPB);

    // Processed layer i uses original layer p = 5 - i.
    // i even: masked half [0,64) (MOFF=0); i odd: MOFF=64.
#define ARGS(p)                                                              \
    P[0] + (p) * 2048, P[1] + (p) * 16,  P[2] + (p) * 256, P[3] + (p) * 16,  \
    P[4] + (p) * 256,  P[5] + (p) * 16,  P[6] + (p) * 256, P[7] + (p) * 16,  \
    P[8] + (p) * 2048, P[9] + (p) * 128,                                     \
    P[10] + (p) * 2048, P[11] + (p) * 16, P[12] + (p) * 256, P[13] + (p) * 16,\
    P[14] + (p) * 256,  P[15] + (p) * 16, P[16] + (p) * 256, P[17] + (p) * 16,\
    P[18] + (p) * 2048, P[19] + (p) * 128

    layer_kernel<0,  true ><<<grid, block>>>(x, ARGS(5), y, ld, B);
    layer_kernel<64, false><<<grid, block>>>(y, ARGS(4), y, ld, B);
    layer_kernel<0,  false><<<grid, block>>>(y, ARGS(3), y, ld, B);
    layer_kernel<64, false><<<grid, block>>>(y, ARGS(2), y, ld, B);
    layer_kernel<0,  false><<<grid, block>>>(y, ARGS(1), y, ld, B);
    layer_kernel<64, false><<<grid, block>>>(y, ARGS(0), y, ld, B);
#undef ARGS
}